// round 13
// baseline (speedup 1.0000x reference)
#include <cuda_runtime.h>
#include <cuda_fp16.h>
#include <math.h>
#include <cstdint>

#define B_DIM   2048
#define HID     512
#define DIM_OUT 256
#define MAXN    128
#define MID_S   256
#define MID_K   320
#define MID_D   384

#define X_SIZE  (2048LL*128*256)
#define N_OFF   X_SIZE
#define MASK_OFF (X_SIZE + 2048LL)

__device__ __align__(16) float g_keys[MAXN * HID];
__device__ int   g_n[B_DIM];
// W1^T fp16, k32 chunks, lane-group interleaved (see prep)
__device__ __align__(16) __half g_W1h[16 * 384 * 32];
__device__ __align__(16) __half g_W2h[12 * 256 * 32];

__device__ __forceinline__ float mishf(float x) {
    float sp = fmaxf(x, 0.f) + log1pf(expf(-fabsf(x)));
    return x * tanhf(sp);
}
__device__ __forceinline__ float mish_fast(float x) {
    float e = __expf(x);
    float y = 1.f + e;
    float d = fmaf(y, y, 1.f);
    return x - 2.f * x * __frcp_rn(d);
}
__device__ __forceinline__ void mma_f16(float* c, const uint32_t* a,
                                        uint32_t b0, uint32_t b1) {
    asm volatile(
        "mma.sync.aligned.m16n8k16.row.col.f32.f16.f16.f32 "
        "{%0,%1,%2,%3}, {%4,%5,%6,%7}, {%8,%9}, {%0,%1,%2,%3};"
        : "+f"(c[0]), "+f"(c[1]), "+f"(c[2]), "+f"(c[3])
        : "r"(a[0]), "r"(a[1]), "r"(a[2]), "r"(a[3]), "r"(b0), "r"(b1));
}
__device__ __forceinline__ void ldsm_x4(uint32_t* r, uint32_t addr) {
    asm volatile(
        "ldmatrix.sync.aligned.m8n8.x4.shared.b16 {%0,%1,%2,%3}, [%4];"
        : "=r"(r[0]), "=r"(r[1]), "=r"(r[2]), "=r"(r[3]) : "r"(addr));
}
__device__ __forceinline__ uint32_t smem_u32(const void* p) {
    uint32_t a;
    asm("{ .reg .u64 t; cvta.to.shared.u64 t, %1; cvt.u32.u64 %0, t; }" : "=r"(a) : "l"(p));
    return a;
}

// ===================== Kernel A: size_pred (16 rows/block, 128 blocks) =========
__global__ __launch_bounds__(256)
void sizepred_kernel(const float* __restrict__ z,
                     const float* __restrict__ W1, const float* __restrict__ b1,
                     const float* __restrict__ g,  const float* __restrict__ be,
                     const float* __restrict__ W2, const float* __restrict__ b2,
                     float* __restrict__ out, int write_n, int write_mask)
{
    __shared__ float zsh[16][HID];                 // 32 KB, aliased as hsh later
    float (*hsh)[MID_S] = (float(*)[MID_S])zsh;    // 16 x 256 alias
    __shared__ float smean[16], srstd[16];
    __shared__ int   nsh[16];
    const int b0  = blockIdx.x * 16;
    const int tid = threadIdx.x;

    #pragma unroll
    for (int e = 0; e < 32; ++e) {
        int lin = e * 256 + tid;
        int bb = lin >> 9, i = lin & 511;
        zsh[bb][i] = z[(size_t)(b0 + bb) * HID + i];
    }
    __syncthreads();

    const int j = tid;
    float acc[16];
    {
        float bj = b1[j];
        #pragma unroll
        for (int bb = 0; bb < 16; ++bb) acc[bb] = bj;
    }
    for (int i = 0; i < HID; i += 4) {
        #pragma unroll
        for (int ii = 0; ii < 4; ++ii) {
            float w = W1[(size_t)(i + ii) * MID_S + j];
            #pragma unroll
            for (int bb = 0; bb < 16; ++bb)
                acc[bb] = fmaf(zsh[bb][i + ii], w, acc[bb]);
        }
    }
    __syncthreads();                 // done reading zsh -> alias safe
    #pragma unroll
    for (int bb = 0; bb < 16; ++bb) hsh[bb][j] = acc[bb];
    __syncthreads();

    const int wid = tid >> 5, lane = tid & 31;
    #pragma unroll
    for (int r2 = 0; r2 < 2; ++r2) {
        int wrow = wid + r2 * 8;
        float s = 0.f, s2 = 0.f;
        for (int jj = lane; jj < MID_S; jj += 32) {
            float v = hsh[wrow][jj];
            s += v; s2 += v * v;
        }
        #pragma unroll
        for (int o = 16; o; o >>= 1) {
            s  += __shfl_xor_sync(0xffffffffu, s,  o);
            s2 += __shfl_xor_sync(0xffffffffu, s2, o);
        }
        if (lane == 0) {
            float m = s * (1.f / MID_S);
            float var = s2 * (1.f / MID_S) - m * m;
            smean[wrow] = m;
            srstd[wrow] = rsqrtf(var + 1e-5f);
        }
    }
    __syncthreads();

    {
        float gj = g[j], bej = be[j], w2j = W2[j];
        #pragma unroll
        for (int bb = 0; bb < 16; ++bb) {
            float v = (acc[bb] - smean[bb]) * srstd[bb] * gj + bej;
            hsh[bb][j] = mishf(v) * w2j;
        }
    }
    __syncthreads();

    #pragma unroll
    for (int r2 = 0; r2 < 2; ++r2) {
        int wrow = wid + r2 * 8;
        float s = 0.f;
        for (int jj = lane; jj < MID_S; jj += 32) s += hsh[wrow][jj];
        #pragma unroll
        for (int o = 16; o; o >>= 1) s += __shfl_xor_sync(0xffffffffu, s, o);
        if (lane == 0) {
            float logit = s + b2[0];
            float nf = fminf(fmaxf(rintf(logit), 0.f), (float)MAXN);
            int ni = (int)nf;
            g_n[b0 + wrow] = ni;
            nsh[wrow] = ni;
            if (write_n) out[N_OFF + b0 + wrow] = nf;
        }
    }
    __syncthreads();

    if (write_mask) {
        #pragma unroll
        for (int e = 0; e < 8; ++e) {
            int lin = e * 256 + tid;
            int bb = lin >> 7, kk = lin & 127;
            out[MASK_OFF + (size_t)(b0 + bb) * MAXN + kk] = (kk < nsh[bb]) ? 1.f : 0.f;
        }
    }
}

// ===================== Fused keys + prep kernel ================================
// blocks [0,128): keys (512 threads). blocks [128, 704): prep (576 * 512 = 294912 ids)
#define W1H_TOTAL (16 * 384 * 32)   // 196608
#define W2H_TOTAL (12 * 256 * 32)   // 98304
__global__ __launch_bounds__(512)
void keysprep_kernel(const float* __restrict__ kW1, const float* __restrict__ kb1,
                     const float* __restrict__ kg,  const float* __restrict__ kbe,
                     const float* __restrict__ kW2, const float* __restrict__ kb2,
                     const float* __restrict__ dW1, const float* __restrict__ dW2)
{
    const int tid = threadIdx.x;
    if (blockIdx.x >= 128) {
        int id = (blockIdx.x - 128) * 512 + tid;
        if (id < W1H_TOTAL) {
            int ktp = id / 12288, rem = id % 12288;
            int nn = rem >> 5, h = rem & 31;
            int tk = h >> 3, pos = h & 7;
            int sub = pos & 3;
            int kl = ((pos >> 2) << 4) + ((sub < 2) ? (2 * tk + sub) : (2 * tk + 8 + sub - 2));
            g_W1h[id] = __float2half_rn(dW1[(size_t)(ktp * 32 + kl) * MID_D + nn]);
        } else if (id < W1H_TOTAL + W2H_TOTAL) {
            int t = id - W1H_TOTAL;
            int ktp = t / 8192, rem = t % 8192;
            int nn = rem >> 5, h = rem & 31;
            int tk = h >> 3, pos = h & 7;
            int sub = pos & 3;
            int kl = ((pos >> 2) << 4) + ((sub < 2) ? (2 * tk + sub) : (2 * tk + 8 + sub - 2));
            g_W2h[t] = __float2half_rn(dW2[(size_t)(ktp * 32 + kl) * DIM_OUT + nn]);
        }
        return;
    }

    // keys branch
    __shared__ float hs[MID_K];
    __shared__ float warp_s[16], warp_s2[16];
    __shared__ float st_mean, st_rstd;
    const int k = blockIdx.x;
    const bool act = tid < MID_K;
    float v = 0.f;
    if (act) v = kW1[(size_t)k * MID_K + tid] + kb1[tid];
    float s = v, s2 = v * v;
    #pragma unroll
    for (int o = 16; o; o >>= 1) {
        s  += __shfl_xor_sync(0xffffffffu, s,  o);
        s2 += __shfl_xor_sync(0xffffffffu, s2, o);
    }
    const int wid = tid >> 5, lane = tid & 31;
    if (lane == 0) { warp_s[wid] = s; warp_s2[wid] = s2; }
    __syncthreads();
    if (wid == 0) {
        float ps  = (lane < 16) ? warp_s[lane]  : 0.f;
        float ps2 = (lane < 16) ? warp_s2[lane] : 0.f;
        #pragma unroll
        for (int o = 8; o; o >>= 1) {
            ps  += __shfl_xor_sync(0xffffffffu, ps,  o);
            ps2 += __shfl_xor_sync(0xffffffffu, ps2, o);
        }
        if (lane == 0) {
            float m = ps * (1.f / MID_K);
            float var = ps2 * (1.f / MID_K) - m * m;
            st_mean = m;
            st_rstd = rsqrtf(var + 1e-5f);
        }
    }
    __syncthreads();
    if (act) hs[tid] = mishf((v - st_mean) * st_rstd * kg[tid] + kbe[tid]);
    __syncthreads();
    const int o = tid;
    float acc = kb2[o];
    for (int jj = 0; jj < MID_K; jj += 4) {
        #pragma unroll
        for (int u = 0; u < 4; ++u)
            acc = fmaf(hs[jj + u], kW2[(size_t)(jj + u) * HID + o], acc);
    }
    g_keys[(size_t)k * HID + o] = acc;
}

// ===================== Kernel C: batch-paired fp16 decoder, 512 threads ========
// Two b-slots per CTA share W streams. Per slot: A [32][520] halves (33280 B),
// H aliased [32][392]. zs: 1024 floats.
#define A_STR 520
#define H_STR 392
#define SLOT_HALVES 16640                    // 32*520
#define SLOT_BYTES  33280
#define ZS_BYTE_OFF 66560                    // 2 slots
#define DEC_SMEM_BYTES (ZS_BYTE_OFF + 4096)  // 70656

__global__ __launch_bounds__(512, 1)
void decoder_kernel(const float* __restrict__ z,
                    const float* __restrict__ b1c,
                    const float* __restrict__ b2c,
                    float* __restrict__ out)
{
    extern __shared__ char smraw[];
    __half* Ah = (__half*)smraw;
    float*  zs = (float*)(smraw + ZS_BYTE_OFF);

    const int bp   = blockIdx.x >> 2;
    const int r0   = (blockIdx.x & 3) * 32;
    const int tid  = threadIdx.x;
    const int wid  = tid >> 5, lane = tid & 31;
    const int ws   = wid >> 3;          // b slot 0/1
    const int wc   = wid & 7;           // col group
    const int tg   = lane >> 2;
    const int tk   = lane & 3;

    const int b0i = 2 * bp, b1i = 2 * bp + 1;
    const int n0 = g_n[b0i], n1 = g_n[b1i];
    const bool alive0 = r0 < n0, alive1 = r0 < n1;
    const int  b_my = ws ? b1i : b0i;
    const int  n_my = ws ? n1 : n0;
    const bool alive_my = ws ? alive1 : alive0;

    if (!alive0 && !alive1) {
        float4 zz = make_float4(0.f, 0.f, 0.f, 0.f);
        float4* o0 = (float4*)(out + (size_t)b0i * MAXN * DIM_OUT + (size_t)r0 * DIM_OUT);
        float4* o1 = (float4*)(out + (size_t)b1i * MAXN * DIM_OUT + (size_t)r0 * DIM_OUT);
        #pragma unroll
        for (int e = 0; e < 4; ++e) {
            o0[e * 512 + tid] = zz;
            o1[e * 512 + tid] = zz;
        }
        return;
    }

    // dead slot: its warps zero-fill their output columns now
    if (!alive_my) {
        float* outd = out + (size_t)b_my * MAXN * DIM_OUT + (size_t)r0 * DIM_OUT;
        float4 zz = make_float4(0.f, 0.f, 0.f, 0.f);
        #pragma unroll
        for (int e = 0; e < 8; ++e) {
            int row = e * 4 + (lane >> 3);
            int c4  = lane & 7;
            *(float4*)(outd + (size_t)row * DIM_OUT + wc * 32 + c4 * 4) = zz;
        }
    }

    zs[tid]       = z[(size_t)b0i * HID + tid];
    zs[512 + tid] = z[(size_t)b1i * HID + tid];
    __syncthreads();

    const float4* K4 = (const float4*)g_keys;
    const float4* Z4 = (const float4*)zs;

    // ---- build A tiles (fp16) for both slots ----
    #pragma unroll
    for (int e = 0; e < 16; ++e) {
        int idx = e * 512 + tid;            // 0..8191
        int s = idx >> 12;                  // slot
        int r = (idx >> 7) & 31;
        int q = idx & 127;
        bool al = s ? alive1 : alive0;
        if (al) {
            float4 kv = K4[(size_t)(r0 + r) * 128 + q];
            float4 zv = Z4[s * 128 + q];
            __half2 h0 = __floats2half2_rn(kv.x * zv.x, kv.y * zv.y);
            __half2 h1 = __floats2half2_rn(kv.z * zv.z, kv.w * zv.w);
            uint2 pk;
            pk.x = *(uint32_t*)&h0;
            pk.y = *(uint32_t*)&h1;
            *(uint2*)(Ah + s * SLOT_HALVES + r * A_STR + q * 4) = pk;
        }
    }
    __syncthreads();   // A visible

    // ldmatrix lane addressing (per slot base)
    const int rowl = lane & 15;
    const int colg = (lane >> 4) << 3;
    const uint32_t smbA = smem_u32(Ah) + (uint32_t)ws * SLOT_BYTES;
    const uint32_t aAddr0 = smbA + (uint32_t)(rowl * A_STR + colg) * 2;
    const uint32_t aAddr1 = smbA + (uint32_t)((16 + rowl) * A_STR + colg) * 2;
    const uint32_t hAddr0 = smbA + (uint32_t)(rowl * H_STR + colg) * 2;
    const uint32_t hAddr1 = smbA + (uint32_t)((16 + rowl) * H_STR + colg) * 2;

    __half* Hh = Ah + ws * SLOT_HALVES;     // slot H alias

    // ================= GEMM1: [32,512] @ W1 -> [32,384] =================
    float c1[2][6][4];
    #pragma unroll
    for (int i = 0; i < 2; ++i)
        #pragma unroll
        for (int jj = 0; jj < 6; ++jj)
            #pragma unroll
            for (int u = 0; u < 4; ++u) c1[i][jj][u] = 0.f;

    if (alive_my) {
        const __half* Wb = g_W1h + ((wc * 48 + tg) << 5) + (tk << 3);
        uint4 bv[6], bn[6];
        #pragma unroll
        for (int jj = 0; jj < 6; ++jj)
            bv[jj] = *(const uint4*)(Wb + jj * 256);

        for (int ktp = 0; ktp < 16; ++ktp) {
            const uint32_t kb = (uint32_t)(ktp << 6);
            uint32_t ae[2][4], ao[2][4];
            ldsm_x4(ae[0], aAddr0 + kb);
            ldsm_x4(ae[1], aAddr1 + kb);
            if (ktp + 1 < 16) {
                const __half* Wn = Wb + (ktp + 1) * 12288;
                #pragma unroll
                for (int jj = 0; jj < 6; ++jj)
                    bn[jj] = *(const uint4*)(Wn + jj * 256);
            }
            #pragma unroll
            for (int jj = 0; jj < 6; ++jj) {
                mma_f16(c1[0][jj], ae[0], bv[jj].x, bv[jj].y);
                mma_f16(c1[1][jj], ae[1], bv[jj].x, bv[jj].y);
            }
            ldsm_x4(ao[0], aAddr0 + kb + 32);
            ldsm_x4(ao[1], aAddr1 + kb + 32);
            #pragma unroll
            for (int jj = 0; jj < 6; ++jj) {
                mma_f16(c1[0][jj], ao[0], bv[jj].z, bv[jj].w);
                mma_f16(c1[1][jj], ao[1], bv[jj].z, bv[jj].w);
            }
            #pragma unroll
            for (int jj = 0; jj < 6; ++jj) bv[jj] = bn[jj];
        }
    }
    __syncthreads();   // all A reads done -> region becomes H

    // ---- epilogue 1: +b1, mish, fp16, store H ----
    if (alive_my) {
        #pragma unroll
        for (int jj = 0; jj < 6; ++jj) {
            int col = wc * 48 + jj * 8 + 2 * tk;
            float bx = __ldg(b1c + col), by = __ldg(b1c + col + 1);
            #pragma unroll
            for (int i = 0; i < 2; ++i) {
                int row = i * 16 + tg;
                __half2 h0 = __floats2half2_rn(mish_fast(c1[i][jj][0] + bx),
                                               mish_fast(c1[i][jj][1] + by));
                __half2 h1 = __floats2half2_rn(mish_fast(c1[i][jj][2] + bx),
                                               mish_fast(c1[i][jj][3] + by));
                *(__half2*)(Hh + row * H_STR + col) = h0;
                *(__half2*)(Hh + (row + 8) * H_STR + col) = h1;
            }
        }
    }
    __syncthreads();   // H visible

    // ================= GEMM2: [32,384] @ W2 -> [32,256] =================
    float c2[2][4][4];
    #pragma unroll
    for (int i = 0; i < 2; ++i)
        #pragma unroll
        for (int jj = 0; jj < 4; ++jj)
            #pragma unroll
            for (int u = 0; u < 4; ++u) c2[i][jj][u] = 0.f;

    if (alive_my) {
        const __half* Wb = g_W2h + ((wc * 32 + tg) << 5) + (tk << 3);
        uint4 bv[4], bn[4];
        #pragma unroll
        for (int jj = 0; jj < 4; ++jj)
            bv[jj] = *(const uint4*)(Wb + jj * 256);

        for (int ktp = 0; ktp < 12; ++ktp) {
            const uint32_t kb = (uint32_t)(ktp << 6);
            uint32_t ae[2][4], ao[2][4];
            ldsm_x4(ae[0], hAddr0 + kb);
            ldsm_x4(ae[1], hAddr1 + kb);
            if (ktp + 1 < 12) {
                const __half* Wn = Wb + (ktp + 1) * 8192;
                #pragma unroll
                for (int jj = 0; jj < 4; ++jj)
                    bn[jj] = *(const uint4*)(Wn + jj * 256);
            }
            #pragma unroll
            for (int jj = 0; jj < 4; ++jj) {
                mma_f16(c2[0][jj], ae[0], bv[jj].x, bv[jj].y);
                mma_f16(c2[1][jj], ae[1], bv[jj].x, bv[jj].y);
            }
            ldsm_x4(ao[0], hAddr0 + kb + 32);
            ldsm_x4(ao[1], hAddr1 + kb + 32);
            #pragma unroll
            for (int jj = 0; jj < 4; ++jj) {
                mma_f16(c2[0][jj], ao[0], bv[jj].z, bv[jj].w);
                mma_f16(c2[1][jj], ao[1], bv[jj].z, bv[jj].w);
            }
            #pragma unroll
            for (int jj = 0; jj < 4; ++jj) bv[jj] = bn[jj];
        }

        // ---- output: +b2, mask, store ----
        float* outb = out + (size_t)b_my * MAXN * DIM_OUT + (size_t)r0 * DIM_OUT;
        #pragma unroll
        for (int jj = 0; jj < 4; ++jj) {
            int col = wc * 32 + jj * 8 + 2 * tk;
            float bx = __ldg(b2c + col), by = __ldg(b2c + col + 1);
            #pragma unroll
            for (int i = 0; i < 2; ++i) {
                int row = i * 16 + tg;
                float2 o0, o1;
                bool v0 = (r0 + row) < n_my, v1 = (r0 + row + 8) < n_my;
                o0.x = v0 ? c2[i][jj][0] + bx : 0.f;
                o0.y = v0 ? c2[i][jj][1] + by : 0.f;
                o1.x = v1 ? c2[i][jj][2] + bx : 0.f;
                o1.y = v1 ? c2[i][jj][3] + by : 0.f;
                *(float2*)(outb + (size_t)row * DIM_OUT + col) = o0;
                *(float2*)(outb + (size_t)(row + 8) * DIM_OUT + col) = o1;
            }
        }
    }
}

// ===================== launch =====================
extern "C" void kernel_launch(void* const* d_in, const int* in_sizes, int n_in,
                              void* d_out, int out_size)
{
    const float* z     = (const float*)d_in[0];
    const float* sp_W1 = (const float*)d_in[1];
    const float* sp_b1 = (const float*)d_in[2];
    const float* sp_g  = (const float*)d_in[3];
    const float* sp_be = (const float*)d_in[4];
    const float* sp_W2 = (const float*)d_in[5];
    const float* sp_b2 = (const float*)d_in[6];
    const float* kn_W1 = (const float*)d_in[7];
    const float* kn_b1 = (const float*)d_in[8];
    const float* kn_g  = (const float*)d_in[9];
    const float* kn_be = (const float*)d_in[10];
    const float* kn_W2 = (const float*)d_in[11];
    const float* kn_b2 = (const float*)d_in[12];
    const float* de_W1 = (const float*)d_in[13];
    const float* de_b1 = (const float*)d_in[14];
    const float* de_W2 = (const float*)d_in[15];
    const float* de_b2 = (const float*)d_in[16];
    float* out = (float*)d_out;

    long long osz = (long long)out_size;
    int write_n    = (osz >= X_SIZE + B_DIM) ? 1 : 0;
    int write_mask = (osz >= X_SIZE + B_DIM + (long long)B_DIM * MAXN) ? 1 : 0;

    cudaFuncSetAttribute(decoder_kernel,
                         cudaFuncAttributeMaxDynamicSharedMemorySize,
                         DEC_SMEM_BYTES);

    sizepred_kernel<<<128, 256>>>(z, sp_W1, sp_b1, sp_g, sp_be, sp_W2, sp_b2,
                                  out, write_n, write_mask);
    keysprep_kernel<<<704, 512>>>(kn_W1, kn_b1, kn_g, kn_be, kn_W2, kn_b2,
                                  de_W1, de_W2);
    decoder_kernel<<<(B_DIM / 2) * 4, 512, DEC_SMEM_BYTES>>>(z, de_b1, de_b2, out);
}

// round 14
// speedup vs baseline: 1.3462x; 1.3462x over previous
#include <cuda_runtime.h>
#include <cuda_fp16.h>
#include <math.h>
#include <cstdint>

#define B_DIM   2048
#define HID     512
#define DIM_OUT 256
#define MAXN    128
#define MID_S   256
#define MID_K   320
#define MID_D   384

#define X_SIZE  (2048LL*128*256)
#define N_OFF   X_SIZE
#define MASK_OFF (X_SIZE + 2048LL)

__device__ __align__(16) float g_keys[MAXN * HID];
__device__ int   g_n[B_DIM];
// W1^T fp16, k32 chunks, lane-group interleaved (see prep branch)
__device__ __align__(16) __half g_W1h[16 * 384 * 32];
__device__ __align__(16) __half g_W2h[12 * 256 * 32];

__device__ __forceinline__ float mishf(float x) {
    float sp = fmaxf(x, 0.f) + log1pf(expf(-fabsf(x)));
    return x * tanhf(sp);
}
__device__ __forceinline__ float rcp_fast(float x) {
    float r;
    asm("rcp.approx.f32 %0, %1;" : "=f"(r) : "f"(x));
    return r;
}
__device__ __forceinline__ float mish_fast(float x) {
    float e = __expf(x);
    float y = 1.f + e;
    float d = fmaf(y, y, 1.f);
    return x - 2.f * x * rcp_fast(d);
}
__device__ __forceinline__ void mma_f16(float* c, const uint32_t* a,
                                        uint32_t b0, uint32_t b1) {
    asm volatile(
        "mma.sync.aligned.m16n8k16.row.col.f32.f16.f16.f32 "
        "{%0,%1,%2,%3}, {%4,%5,%6,%7}, {%8,%9}, {%0,%1,%2,%3};"
        : "+f"(c[0]), "+f"(c[1]), "+f"(c[2]), "+f"(c[3])
        : "r"(a[0]), "r"(a[1]), "r"(a[2]), "r"(a[3]), "r"(b0), "r"(b1));
}
__device__ __forceinline__ void ldsm_x4(uint32_t* r, uint32_t addr) {
    asm volatile(
        "ldmatrix.sync.aligned.m8n8.x4.shared.b16 {%0,%1,%2,%3}, [%4];"
        : "=r"(r[0]), "=r"(r[1]), "=r"(r[2]), "=r"(r[3]) : "r"(addr));
}
__device__ __forceinline__ uint32_t smem_u32(const void* p) {
    uint32_t a;
    asm("{ .reg .u64 t; cvta.to.shared.u64 t, %1; cvt.u32.u64 %0, t; }" : "=r"(a) : "l"(p));
    return a;
}

// ===================== Kernel A: size_pred (8 rows/block, 256 blocks) ==========
__global__ __launch_bounds__(256)
void sizepred_kernel(const float* __restrict__ z,
                     const float* __restrict__ W1, const float* __restrict__ b1,
                     const float* __restrict__ g,  const float* __restrict__ be,
                     const float* __restrict__ W2, const float* __restrict__ b2,
                     float* __restrict__ out, int write_n, int write_mask)
{
    __shared__ float zsh[8][HID];
    __shared__ float hsh[8][MID_S];
    __shared__ float smean[8], srstd[8];
    __shared__ int   nsh[8];
    const int b0  = blockIdx.x * 8;
    const int tid = threadIdx.x;

    #pragma unroll
    for (int e = 0; e < 16; ++e) {
        int lin = e * 256 + tid;
        int bb = lin >> 9, i = lin & 511;
        zsh[bb][i] = z[(size_t)(b0 + bb) * HID + i];
    }
    __syncthreads();

    const int j = tid;
    float acc[8];
    {
        float bj = b1[j];
        #pragma unroll
        for (int bb = 0; bb < 8; ++bb) acc[bb] = bj;
    }
    for (int i = 0; i < HID; i += 8) {
        #pragma unroll
        for (int ii = 0; ii < 8; ++ii) {
            float w = W1[(size_t)(i + ii) * MID_S + j];
            #pragma unroll
            for (int bb = 0; bb < 8; ++bb)
                acc[bb] = fmaf(zsh[bb][i + ii], w, acc[bb]);
        }
    }
    #pragma unroll
    for (int bb = 0; bb < 8; ++bb) hsh[bb][j] = acc[bb];
    __syncthreads();

    const int wrow = tid >> 5, lane = tid & 31;
    {
        float s = 0.f, s2 = 0.f;
        for (int jj = lane; jj < MID_S; jj += 32) {
            float v = hsh[wrow][jj];
            s += v; s2 += v * v;
        }
        #pragma unroll
        for (int o = 16; o; o >>= 1) {
            s  += __shfl_xor_sync(0xffffffffu, s,  o);
            s2 += __shfl_xor_sync(0xffffffffu, s2, o);
        }
        if (lane == 0) {
            float m = s * (1.f / MID_S);
            float var = s2 * (1.f / MID_S) - m * m;
            smean[wrow] = m;
            srstd[wrow] = rsqrtf(var + 1e-5f);
        }
    }
    __syncthreads();

    {
        float gj = g[j], bej = be[j], w2j = W2[j];
        #pragma unroll
        for (int bb = 0; bb < 8; ++bb) {
            float v = (acc[bb] - smean[bb]) * srstd[bb] * gj + bej;
            hsh[bb][j] = mishf(v) * w2j;
        }
    }
    __syncthreads();

    {
        float s = 0.f;
        for (int jj = lane; jj < MID_S; jj += 32) s += hsh[wrow][jj];
        #pragma unroll
        for (int o = 16; o; o >>= 1) s += __shfl_xor_sync(0xffffffffu, s, o);
        if (lane == 0) {
            float logit = s + b2[0];
            float nf = fminf(fmaxf(rintf(logit), 0.f), (float)MAXN);
            int ni = (int)nf;
            g_n[b0 + wrow] = ni;
            nsh[wrow] = ni;
            if (write_n) out[N_OFF + b0 + wrow] = nf;
        }
    }
    __syncthreads();

    if (write_mask) {
        #pragma unroll
        for (int e = 0; e < 4; ++e) {
            int lin = e * 256 + tid;
            int bb = lin >> 7, kk = lin & 127;
            out[MASK_OFF + (size_t)(b0 + bb) * MAXN + kk] = (kk < nsh[bb]) ? 1.f : 0.f;
        }
    }
}

// ===================== Fused keys + prep kernel ================================
// blocks [0,128): keys (512 threads). blocks [128,704): prep (576*512 ids)
#define W1H_TOTAL (16 * 384 * 32)   // 196608
#define W2H_TOTAL (12 * 256 * 32)   // 98304
__global__ __launch_bounds__(512)
void keysprep_kernel(const float* __restrict__ kW1, const float* __restrict__ kb1,
                     const float* __restrict__ kg,  const float* __restrict__ kbe,
                     const float* __restrict__ kW2, const float* __restrict__ kb2,
                     const float* __restrict__ dW1, const float* __restrict__ dW2)
{
    const int tid = threadIdx.x;
    if (blockIdx.x >= 128) {
        int id = (blockIdx.x - 128) * 512 + tid;
        if (id < W1H_TOTAL) {
            int ktp = id / 12288, rem = id % 12288;
            int nn = rem >> 5, h = rem & 31;
            int tk = h >> 3, pos = h & 7;
            int sub = pos & 3;
            int kl = ((pos >> 2) << 4) + ((sub < 2) ? (2 * tk + sub) : (2 * tk + 8 + sub - 2));
            g_W1h[id] = __float2half_rn(dW1[(size_t)(ktp * 32 + kl) * MID_D + nn]);
        } else if (id < W1H_TOTAL + W2H_TOTAL) {
            int t = id - W1H_TOTAL;
            int ktp = t / 8192, rem = t % 8192;
            int nn = rem >> 5, h = rem & 31;
            int tk = h >> 3, pos = h & 7;
            int sub = pos & 3;
            int kl = ((pos >> 2) << 4) + ((sub < 2) ? (2 * tk + sub) : (2 * tk + 8 + sub - 2));
            g_W2h[t] = __float2half_rn(dW2[(size_t)(ktp * 32 + kl) * DIM_OUT + nn]);
        }
        return;
    }

    // ---- keys branch ----
    __shared__ float hs[MID_K];
    __shared__ float warp_s[16], warp_s2[16];
    __shared__ float st_mean, st_rstd;
    const int k = blockIdx.x;
    const bool act = tid < MID_K;
    float v = 0.f;
    if (act) v = kW1[(size_t)k * MID_K + tid] + kb1[tid];
    float s = v, s2 = v * v;
    #pragma unroll
    for (int o = 16; o; o >>= 1) {
        s  += __shfl_xor_sync(0xffffffffu, s,  o);
        s2 += __shfl_xor_sync(0xffffffffu, s2, o);
    }
    const int wid = tid >> 5, lane = tid & 31;
    if (lane == 0) { warp_s[wid] = s; warp_s2[wid] = s2; }
    __syncthreads();
    if (wid == 0) {
        float ps  = (lane < 16) ? warp_s[lane]  : 0.f;
        float ps2 = (lane < 16) ? warp_s2[lane] : 0.f;
        #pragma unroll
        for (int o = 8; o; o >>= 1) {
            ps  += __shfl_xor_sync(0xffffffffu, ps,  o);
            ps2 += __shfl_xor_sync(0xffffffffu, ps2, o);
        }
        if (lane == 0) {
            float m = ps * (1.f / MID_K);
            float var = ps2 * (1.f / MID_K) - m * m;
            st_mean = m;
            st_rstd = rsqrtf(var + 1e-5f);
        }
    }
    __syncthreads();
    if (act) hs[tid] = mishf((v - st_mean) * st_rstd * kg[tid] + kbe[tid]);
    __syncthreads();
    const int o = tid;
    float acc = kb2[o];
    for (int jj = 0; jj < MID_K; jj += 4) {
        #pragma unroll
        for (int u = 0; u < 4; ++u)
            acc = fmaf(hs[jj + u], kW2[(size_t)(jj + u) * HID + o], acc);
    }
    g_keys[(size_t)k * HID + o] = acc;
}

// ===================== Kernel C: fp16 mma decoder + ldmatrix, 2 CTAs/SM ========
// A smem: [32 rows][520 halves]; rows 1040 B apart -> 260 words, 260%32=4 ->
// ldmatrix 8-row phases hit disjoint bank quads (conflict-free). H: [32][392].
#define A_STR 520
#define H_STR 392
#define ZS_BYTE_OFF 33280                    // 32*520*2
#define DEC_SMEM_BYTES (ZS_BYTE_OFF + 2048)  // 35328

__global__ __launch_bounds__(256, 2)
void decoder_kernel(const float* __restrict__ z,
                    const float* __restrict__ b1c,
                    const float* __restrict__ b2c,
                    float* __restrict__ out)
{
    extern __shared__ char smraw[];
    __half* Ah = (__half*)smraw;
    __half* Hh = (__half*)smraw;
    float*  zs = (float*)(smraw + ZS_BYTE_OFF);

    const int b    = blockIdx.x >> 2;
    const int r0   = (blockIdx.x & 3) * 32;
    const int tid  = threadIdx.x;
    const int wc   = tid >> 5;          // 0..7 warp col
    const int lane = tid & 31;
    const int tg   = lane >> 2;         // 0..7
    const int tk   = lane & 3;          // 0..3

    const int n = g_n[b];
    float* outb = out + (size_t)b * MAXN * DIM_OUT + (size_t)r0 * DIM_OUT;

    if (r0 >= n) {
        float4 zz = make_float4(0.f, 0.f, 0.f, 0.f);
        float4* o4 = (float4*)outb;
        #pragma unroll
        for (int e = 0; e < 8; ++e) o4[e * 256 + tid] = zz;
        return;
    }

    zs[tid] = z[(size_t)b * HID + tid];
    zs[256 + tid] = z[(size_t)b * HID + 256 + tid];
    __syncthreads();

    const float4* K4 = (const float4*)g_keys;
    const float4* Z4 = (const float4*)zs;

    // ---- build A (fp16): A[r][k] = half(keys[r0+r][k] * z[k]) ----
    #pragma unroll
    for (int e = 0; e < 16; ++e) {
        int idx = e * 256 + tid;        // 0..4095
        int r = idx >> 7, q = idx & 127;
        float4 kv = K4[(size_t)(r0 + r) * 128 + q];
        float4 zv = Z4[q];
        __half2 h0 = __floats2half2_rn(kv.x * zv.x, kv.y * zv.y);
        __half2 h1 = __floats2half2_rn(kv.z * zv.z, kv.w * zv.w);
        uint2 pk;
        pk.x = *(uint32_t*)&h0;
        pk.y = *(uint32_t*)&h1;
        *(uint2*)(Ah + r * A_STR + q * 4) = pk;
    }
    __syncthreads();   // A visible

    // ldmatrix lane addressing: lanes 0-15 -> rows 0-15 col k0;
    // lanes 16-31 -> rows 0-15 col k0+8
    const int rowl = lane & 15;
    const int colg = (lane >> 4) << 3;
    const uint32_t smbA = smem_u32(Ah);
    const uint32_t aAddr0 = smbA + (uint32_t)(rowl * A_STR + colg) * 2;
    const uint32_t aAddr1 = smbA + (uint32_t)((16 + rowl) * A_STR + colg) * 2;
    const uint32_t hAddr0 = smbA + (uint32_t)(rowl * H_STR + colg) * 2;
    const uint32_t hAddr1 = smbA + (uint32_t)((16 + rowl) * H_STR + colg) * 2;

    // ================= GEMM1: [32,512] @ W1 -> [32,384] =================
    float c1[2][6][4];
    #pragma unroll
    for (int i = 0; i < 2; ++i)
        #pragma unroll
        for (int jj = 0; jj < 6; ++jj)
            #pragma unroll
            for (int u = 0; u < 4; ++u) c1[i][jj][u] = 0.f;

    {
        const __half* Wb = g_W1h + ((wc * 48 + tg) << 5) + (tk << 3);
        uint4 bv[6], bn[6];
        #pragma unroll
        for (int jj = 0; jj < 6; ++jj)
            bv[jj] = *(const uint4*)(Wb + jj * 256);

        for (int ktp = 0; ktp < 16; ++ktp) {
            const uint32_t kb = (uint32_t)(ktp << 6);   // k0*2 bytes
            uint32_t ae[2][4], ao[2][4];
            ldsm_x4(ae[0], aAddr0 + kb);
            ldsm_x4(ae[1], aAddr1 + kb);
            if (ktp + 1 < 16) {
                const __half* Wn = Wb + (ktp + 1) * 12288;
                #pragma unroll
                for (int jj = 0; jj < 6; ++jj)
                    bn[jj] = *(const uint4*)(Wn + jj * 256);
            }
            #pragma unroll
            for (int jj = 0; jj < 6; ++jj) {
                mma_f16(c1[0][jj], ae[0], bv[jj].x, bv[jj].y);
                mma_f16(c1[1][jj], ae[1], bv[jj].x, bv[jj].y);
            }
            ldsm_x4(ao[0], aAddr0 + kb + 32);
            ldsm_x4(ao[1], aAddr1 + kb + 32);
            #pragma unroll
            for (int jj = 0; jj < 6; ++jj) {
                mma_f16(c1[0][jj], ao[0], bv[jj].z, bv[jj].w);
                mma_f16(c1[1][jj], ao[1], bv[jj].z, bv[jj].w);
            }
            #pragma unroll
            for (int jj = 0; jj < 6; ++jj) bv[jj] = bn[jj];
        }
    }
    __syncthreads();   // all A reads done -> region becomes H

    // ---- epilogue 1: +b1, mish, fp16, store H ----
    #pragma unroll
    for (int jj = 0; jj < 6; ++jj) {
        int col = wc * 48 + jj * 8 + 2 * tk;
        float bx = __ldg(b1c + col), by = __ldg(b1c + col + 1);
        #pragma unroll
        for (int i = 0; i < 2; ++i) {
            int row = i * 16 + tg;
            __half2 h0 = __floats2half2_rn(mish_fast(c1[i][jj][0] + bx),
                                           mish_fast(c1[i][jj][1] + by));
            __half2 h1 = __floats2half2_rn(mish_fast(c1[i][jj][2] + bx),
                                           mish_fast(c1[i][jj][3] + by));
            *(__half2*)(Hh + row * H_STR + col) = h0;
            *(__half2*)(Hh + (row + 8) * H_STR + col) = h1;
        }
    }
    __syncthreads();   // H visible

    // ================= GEMM2: [32,384] @ W2 -> [32,256] =================
    float c2[2][4][4];
    #pragma unroll
    for (int i = 0; i < 2; ++i)
        #pragma unroll
        for (int jj = 0; jj < 4; ++jj)
            #pragma unroll
            for (int u = 0; u < 4; ++u) c2[i][jj][u] = 0.f;

    {
        const __half* Wb = g_W2h + ((wc * 32 + tg) << 5) + (tk << 3);
        uint4 bv[4], bn[4];
        #pragma unroll
        for (int jj = 0; jj < 4; ++jj)
            bv[jj] = *(const uint4*)(Wb + jj * 256);

        for (int ktp = 0; ktp < 12; ++ktp) {
            const uint32_t kb = (uint32_t)(ktp << 6);
            uint32_t ae[2][4], ao[2][4];
            ldsm_x4(ae[0], hAddr0 + kb);
            ldsm_x4(ae[1], hAddr1 + kb);
            if (ktp + 1 < 12) {
                const __half* Wn = Wb + (ktp + 1) * 8192;
                #pragma unroll
                for (int jj = 0; jj < 4; ++jj)
                    bn[jj] = *(const uint4*)(Wn + jj * 256);
            }
            #pragma unroll
            for (int jj = 0; jj < 4; ++jj) {
                mma_f16(c2[0][jj], ae[0], bv[jj].x, bv[jj].y);
                mma_f16(c2[1][jj], ae[1], bv[jj].x, bv[jj].y);
            }
            ldsm_x4(ao[0], hAddr0 + kb + 32);
            ldsm_x4(ao[1], hAddr1 + kb + 32);
            #pragma unroll
            for (int jj = 0; jj < 4; ++jj) {
                mma_f16(c2[0][jj], ao[0], bv[jj].z, bv[jj].w);
                mma_f16(c2[1][jj], ao[1], bv[jj].z, bv[jj].w);
            }
            #pragma unroll
            for (int jj = 0; jj < 4; ++jj) bv[jj] = bn[jj];
        }
    }

    // ---- output: +b2, mask, store ----
    #pragma unroll
    for (int jj = 0; jj < 4; ++jj) {
        int col = wc * 32 + jj * 8 + 2 * tk;
        float bx = __ldg(b2c + col), by = __ldg(b2c + col + 1);
        #pragma unroll
        for (int i = 0; i < 2; ++i) {
            int row = i * 16 + tg;
            float2 o0, o1;
            bool v0 = (r0 + row) < n, v1 = (r0 + row + 8) < n;
            o0.x = v0 ? c2[i][jj][0] + bx : 0.f;
            o0.y = v0 ? c2[i][jj][1] + by : 0.f;
            o1.x = v1 ? c2[i][jj][2] + bx : 0.f;
            o1.y = v1 ? c2[i][jj][3] + by : 0.f;
            *(float2*)(outb + (size_t)row * DIM_OUT + col) = o0;
            *(float2*)(outb + (size_t)(row + 8) * DIM_OUT + col) = o1;
        }
    }
}

// ===================== launch =====================
extern "C" void kernel_launch(void* const* d_in, const int* in_sizes, int n_in,
                              void* d_out, int out_size)
{
    const float* z     = (const float*)d_in[0];
    const float* sp_W1 = (const float*)d_in[1];
    const float* sp_b1 = (const float*)d_in[2];
    const float* sp_g  = (const float*)d_in[3];
    const float* sp_be = (const float*)d_in[4];
    const float* sp_W2 = (const float*)d_in[5];
    const float* sp_b2 = (const float*)d_in[6];
    const float* kn_W1 = (const float*)d_in[7];
    const float* kn_b1 = (const float*)d_in[8];
    const float* kn_g  = (const float*)d_in[9];
    const float* kn_be = (const float*)d_in[10];
    const float* kn_W2 = (const float*)d_in[11];
    const float* kn_b2 = (const float*)d_in[12];
    const float* de_W1 = (const float*)d_in[13];
    const float* de_b1 = (const float*)d_in[14];
    const float* de_W2 = (const float*)d_in[15];
    const float* de_b2 = (const float*)d_in[16];
    float* out = (float*)d_out;

    long long osz = (long long)out_size;
    int write_n    = (osz >= X_SIZE + B_DIM) ? 1 : 0;
    int write_mask = (osz >= X_SIZE + B_DIM + (long long)B_DIM * MAXN) ? 1 : 0;

    cudaFuncSetAttribute(decoder_kernel,
                         cudaFuncAttributeMaxDynamicSharedMemorySize,
                         DEC_SMEM_BYTES);

    sizepred_kernel<<<256, 256>>>(z, sp_W1, sp_b1, sp_g, sp_be, sp_W2, sp_b2,
                                  out, write_n, write_mask);
    keysprep_kernel<<<704, 512>>>(kn_W1, kn_b1, kn_g, kn_be, kn_W2, kn_b2,
                                  de_W1, de_W2);
    decoder_kernel<<<B_DIM * 4, 256, DEC_SMEM_BYTES>>>(z, de_b1, de_b2, out);
}

// round 15
// speedup vs baseline: 1.4471x; 1.0749x over previous
#include <cuda_runtime.h>
#include <cuda_fp16.h>
#include <math.h>
#include <cstdint>

#define B_DIM   2048
#define HID     512
#define DIM_OUT 256
#define MAXN    128
#define MID_S   256
#define MID_K   320
#define MID_D   384

#define X_SIZE  (2048LL*128*256)
#define N_OFF   X_SIZE
#define MASK_OFF (X_SIZE + 2048LL)

__device__ __align__(16) float g_keys[MAXN * HID];
__device__ int   g_n[B_DIM];
// W1^T fp16, k32 chunks, lane-group interleaved (see prep branch)
__device__ __align__(16) __half g_W1h[16 * 384 * 32];
__device__ __align__(16) __half g_W2h[12 * 256 * 32];

__device__ __forceinline__ float mishf(float x) {
    float sp = fmaxf(x, 0.f) + log1pf(expf(-fabsf(x)));
    return x * tanhf(sp);
}
__device__ __forceinline__ float rcp_fast(float x) {
    float r;
    asm("rcp.approx.f32 %0, %1;" : "=f"(r) : "f"(x));
    return r;
}
__device__ __forceinline__ float mish_fast(float x) {
    float e = __expf(x);
    float y = 1.f + e;
    float d = fmaf(y, y, 1.f);
    return x - 2.f * x * rcp_fast(d);
}
__device__ __forceinline__ void mma_f16(float* c, const uint32_t* a,
                                        uint32_t b0, uint32_t b1) {
    asm volatile(
        "mma.sync.aligned.m16n8k16.row.col.f32.f16.f16.f32 "
        "{%0,%1,%2,%3}, {%4,%5,%6,%7}, {%8,%9}, {%0,%1,%2,%3};"
        : "+f"(c[0]), "+f"(c[1]), "+f"(c[2]), "+f"(c[3])
        : "r"(a[0]), "r"(a[1]), "r"(a[2]), "r"(a[3]), "r"(b0), "r"(b1));
}
__device__ __forceinline__ void ldsm_x4(uint32_t* r, uint32_t addr) {
    asm volatile(
        "ldmatrix.sync.aligned.m8n8.x4.shared.b16 {%0,%1,%2,%3}, [%4];"
        : "=r"(r[0]), "=r"(r[1]), "=r"(r[2]), "=r"(r[3]) : "r"(addr));
}
__device__ __forceinline__ uint32_t smem_u32(const void* p) {
    uint32_t a;
    asm("{ .reg .u64 t; cvta.to.shared.u64 t, %1; cvt.u32.u64 %0, t; }" : "=r"(a) : "l"(p));
    return a;
}

// ===================== Kernel A: size_pred, split-K (512 thr, 8 rows/block) ====
__global__ __launch_bounds__(512)
void sizepred_kernel(const float* __restrict__ z,
                     const float* __restrict__ W1, const float* __restrict__ b1,
                     const float* __restrict__ g,  const float* __restrict__ be,
                     const float* __restrict__ W2, const float* __restrict__ b2,
                     float* __restrict__ out, int write_n, int write_mask)
{
    __shared__ float zsh[8][HID];       // 16 KB
    __shared__ float hsh[8][MID_S];     // 8 KB (kh=0 partial, then full sum)
    __shared__ float ps[8][MID_S];      // 8 KB (kh=1 partial)
    __shared__ float smean[8], srstd[8];
    __shared__ int   nsh[8];
    const int b0  = blockIdx.x * 8;
    const int tid = threadIdx.x;

    // load 8 z rows (float4, 1024 loads)
    {
        const float4* z4 = (const float4*)(z + (size_t)b0 * HID);
        float4* zs4 = (float4*)zsh;
        #pragma unroll
        for (int e = 0; e < 2; ++e) zs4[e * 512 + tid] = z4[e * 512 + tid];
    }
    __syncthreads();

    const int j  = tid & 255;
    const int kh = tid >> 8;            // K half 0/1
    float acc[8];
    {
        float bj = (kh == 0) ? b1[j] : 0.f;
        #pragma unroll
        for (int bb = 0; bb < 8; ++bb) acc[bb] = bj;
    }
    const int kbase = kh * 256;
    for (int i = 0; i < 256; i += 8) {
        #pragma unroll
        for (int ii = 0; ii < 8; ++ii) {
            float w = W1[(size_t)(kbase + i + ii) * MID_S + j];
            #pragma unroll
            for (int bb = 0; bb < 8; ++bb)
                acc[bb] = fmaf(zsh[bb][kbase + i + ii], w, acc[bb]);
        }
    }
    {
        float (*dst)[MID_S] = (kh == 0) ? hsh : ps;
        #pragma unroll
        for (int bb = 0; bb < 8; ++bb) dst[bb][j] = acc[bb];
    }
    __syncthreads();

    // combine partials (kh=0 threads)
    if (kh == 0) {
        #pragma unroll
        for (int bb = 0; bb < 8; ++bb) hsh[bb][j] += ps[bb][j];
    }
    __syncthreads();

    const int wid = tid >> 5, lane = tid & 31;
    // stats: warps 0..7, one row each
    if (wid < 8) {
        float s = 0.f, s2 = 0.f;
        for (int jj = lane; jj < MID_S; jj += 32) {
            float v = hsh[wid][jj];
            s += v; s2 += v * v;
        }
        #pragma unroll
        for (int o = 16; o; o >>= 1) {
            s  += __shfl_xor_sync(0xffffffffu, s,  o);
            s2 += __shfl_xor_sync(0xffffffffu, s2, o);
        }
        if (lane == 0) {
            float m = s * (1.f / MID_S);
            float var = s2 * (1.f / MID_S) - m * m;
            smean[wid] = m;
            srstd[wid] = rsqrtf(var + 1e-5f);
        }
    }
    __syncthreads();

    // layernorm + mish + *W2 : 2048 elems over 512 threads
    #pragma unroll
    for (int e = 0; e < 4; ++e) {
        int lin = e * 512 + tid;
        int bb = lin >> 8, jj = lin & 255;
        float v = (hsh[bb][jj] - smean[bb]) * srstd[bb] * g[jj] + be[jj];
        hsh[bb][jj] = mishf(v) * W2[jj];
    }
    __syncthreads();

    // logit sums: warps 0..7
    if (wid < 8) {
        float s = 0.f;
        for (int jj = lane; jj < MID_S; jj += 32) s += hsh[wid][jj];
        #pragma unroll
        for (int o = 16; o; o >>= 1) s += __shfl_xor_sync(0xffffffffu, s, o);
        if (lane == 0) {
            float logit = s + b2[0];
            float nf = fminf(fmaxf(rintf(logit), 0.f), (float)MAXN);
            int ni = (int)nf;
            g_n[b0 + wid] = ni;
            nsh[wid] = ni;
            if (write_n) out[N_OFF + b0 + wid] = nf;
        }
    }
    __syncthreads();

    if (write_mask) {
        #pragma unroll
        for (int e = 0; e < 2; ++e) {
            int lin = e * 512 + tid;
            int bb = lin >> 7, kk = lin & 127;
            out[MASK_OFF + (size_t)(b0 + bb) * MAXN + kk] = (kk < nsh[bb]) ? 1.f : 0.f;
        }
    }
}

// ===================== Fused keys + prep kernel ================================
// blocks [0,128): keys (512 threads). blocks [128,704): prep (576*512 ids)
#define W1H_TOTAL (16 * 384 * 32)   // 196608
#define W2H_TOTAL (12 * 256 * 32)   // 98304
__global__ __launch_bounds__(512)
void keysprep_kernel(const float* __restrict__ kW1, const float* __restrict__ kb1,
                     const float* __restrict__ kg,  const float* __restrict__ kbe,
                     const float* __restrict__ kW2, const float* __restrict__ kb2,
                     const float* __restrict__ dW1, const float* __restrict__ dW2)
{
    const int tid = threadIdx.x;
    if (blockIdx.x >= 128) {
        int id = (blockIdx.x - 128) * 512 + tid;
        if (id < W1H_TOTAL) {
            int ktp = id / 12288, rem = id % 12288;
            int nn = rem >> 5, h = rem & 31;
            int tk = h >> 3, pos = h & 7;
            int sub = pos & 3;
            int kl = ((pos >> 2) << 4) + ((sub < 2) ? (2 * tk + sub) : (2 * tk + 8 + sub - 2));
            g_W1h[id] = __float2half_rn(dW1[(size_t)(ktp * 32 + kl) * MID_D + nn]);
        } else if (id < W1H_TOTAL + W2H_TOTAL) {
            int t = id - W1H_TOTAL;
            int ktp = t / 8192, rem = t % 8192;
            int nn = rem >> 5, h = rem & 31;
            int tk = h >> 3, pos = h & 7;
            int sub = pos & 3;
            int kl = ((pos >> 2) << 4) + ((sub < 2) ? (2 * tk + sub) : (2 * tk + 8 + sub - 2));
            g_W2h[t] = __float2half_rn(dW2[(size_t)(ktp * 32 + kl) * DIM_OUT + nn]);
        }
        return;
    }

    // ---- keys branch ----
    __shared__ float hs[MID_K];
    __shared__ float warp_s[16], warp_s2[16];
    __shared__ float st_mean, st_rstd;
    const int k = blockIdx.x;
    const bool act = tid < MID_K;
    float v = 0.f;
    if (act) v = kW1[(size_t)k * MID_K + tid] + kb1[tid];
    float s = v, s2 = v * v;
    #pragma unroll
    for (int o = 16; o; o >>= 1) {
        s  += __shfl_xor_sync(0xffffffffu, s,  o);
        s2 += __shfl_xor_sync(0xffffffffu, s2, o);
    }
    const int wid = tid >> 5, lane = tid & 31;
    if (lane == 0) { warp_s[wid] = s; warp_s2[wid] = s2; }
    __syncthreads();
    if (wid == 0) {
        float ps  = (lane < 16) ? warp_s[lane]  : 0.f;
        float ps2 = (lane < 16) ? warp_s2[lane] : 0.f;
        #pragma unroll
        for (int o = 8; o; o >>= 1) {
            ps  += __shfl_xor_sync(0xffffffffu, ps,  o);
            ps2 += __shfl_xor_sync(0xffffffffu, ps2, o);
        }
        if (lane == 0) {
            float m = ps * (1.f / MID_K);
            float var = ps2 * (1.f / MID_K) - m * m;
            st_mean = m;
            st_rstd = rsqrtf(var + 1e-5f);
        }
    }
    __syncthreads();
    if (act) hs[tid] = mishf((v - st_mean) * st_rstd * kg[tid] + kbe[tid]);
    __syncthreads();
    const int o = tid;
    float acc = kb2[o];
    for (int jj = 0; jj < MID_K; jj += 4) {
        #pragma unroll
        for (int u = 0; u < 4; ++u)
            acc = fmaf(hs[jj + u], kW2[(size_t)(jj + u) * HID + o], acc);
    }
    g_keys[(size_t)k * HID + o] = acc;
}

// ===================== Kernel C: fp16 mma decoder + ldmatrix, 2 CTAs/SM ========
// A smem: [32 rows][520 halves]; rows 1040 B apart -> 260 words, 260%32=4 ->
// ldmatrix 8-row phases hit disjoint bank quads (conflict-free). H: [32][392].
#define A_STR 520
#define H_STR 392
#define ZS_BYTE_OFF 33280                    // 32*520*2
#define DEC_SMEM_BYTES (ZS_BYTE_OFF + 2048)  // 35328

__global__ __launch_bounds__(256, 2)
void decoder_kernel(const float* __restrict__ z,
                    const float* __restrict__ b1c,
                    const float* __restrict__ b2c,
                    float* __restrict__ out)
{
    extern __shared__ char smraw[];
    __half* Ah = (__half*)smraw;
    __half* Hh = (__half*)smraw;
    float*  zs = (float*)(smraw + ZS_BYTE_OFF);

    const int b    = blockIdx.x >> 2;
    const int r0   = (blockIdx.x & 3) * 32;
    const int tid  = threadIdx.x;
    const int wc   = tid >> 5;          // 0..7 warp col
    const int lane = tid & 31;
    const int tg   = lane >> 2;         // 0..7
    const int tk   = lane & 3;          // 0..3

    const int n = g_n[b];
    float* outb = out + (size_t)b * MAXN * DIM_OUT + (size_t)r0 * DIM_OUT;

    if (r0 >= n) {
        float4 zz = make_float4(0.f, 0.f, 0.f, 0.f);
        float4* o4 = (float4*)outb;
        #pragma unroll
        for (int e = 0; e < 8; ++e) o4[e * 256 + tid] = zz;
        return;
    }

    zs[tid] = z[(size_t)b * HID + tid];
    zs[256 + tid] = z[(size_t)b * HID + 256 + tid];
    __syncthreads();

    const float4* K4 = (const float4*)g_keys;
    const float4* Z4 = (const float4*)zs;

    // ---- build A (fp16): A[r][k] = half(keys[r0+r][k] * z[k]) ----
    #pragma unroll
    for (int e = 0; e < 16; ++e) {
        int idx = e * 256 + tid;        // 0..4095
        int r = idx >> 7, q = idx & 127;
        float4 kv = K4[(size_t)(r0 + r) * 128 + q];
        float4 zv = Z4[q];
        __half2 h0 = __floats2half2_rn(kv.x * zv.x, kv.y * zv.y);
        __half2 h1 = __floats2half2_rn(kv.z * zv.z, kv.w * zv.w);
        uint2 pk;
        pk.x = *(uint32_t*)&h0;
        pk.y = *(uint32_t*)&h1;
        *(uint2*)(Ah + r * A_STR + q * 4) = pk;
    }
    __syncthreads();   // A visible

    // ldmatrix lane addressing
    const int rowl = lane & 15;
    const int colg = (lane >> 4) << 3;
    const uint32_t smbA = smem_u32(Ah);
    const uint32_t aAddr0 = smbA + (uint32_t)(rowl * A_STR + colg) * 2;
    const uint32_t aAddr1 = smbA + (uint32_t)((16 + rowl) * A_STR + colg) * 2;
    const uint32_t hAddr0 = smbA + (uint32_t)(rowl * H_STR + colg) * 2;
    const uint32_t hAddr1 = smbA + (uint32_t)((16 + rowl) * H_STR + colg) * 2;

    // ================= GEMM1: [32,512] @ W1 -> [32,384] =================
    float c1[2][6][4];
    #pragma unroll
    for (int i = 0; i < 2; ++i)
        #pragma unroll
        for (int jj = 0; jj < 6; ++jj)
            #pragma unroll
            for (int u = 0; u < 4; ++u) c1[i][jj][u] = 0.f;

    {
        const __half* Wb = g_W1h + ((wc * 48 + tg) << 5) + (tk << 3);
        uint4 bv[6], bn[6];
        #pragma unroll
        for (int jj = 0; jj < 6; ++jj)
            bv[jj] = *(const uint4*)(Wb + jj * 256);

        for (int ktp = 0; ktp < 16; ++ktp) {
            const uint32_t kb = (uint32_t)(ktp << 6);   // k0*2 bytes
            uint32_t ae[2][4], ao[2][4];
            ldsm_x4(ae[0], aAddr0 + kb);
            ldsm_x4(ae[1], aAddr1 + kb);
            if (ktp + 1 < 16) {
                const __half* Wn = Wb + (ktp + 1) * 12288;
                #pragma unroll
                for (int jj = 0; jj < 6; ++jj)
                    bn[jj] = *(const uint4*)(Wn + jj * 256);
            }
            #pragma unroll
            for (int jj = 0; jj < 6; ++jj) {
                mma_f16(c1[0][jj], ae[0], bv[jj].x, bv[jj].y);
                mma_f16(c1[1][jj], ae[1], bv[jj].x, bv[jj].y);
            }
            ldsm_x4(ao[0], aAddr0 + kb + 32);
            ldsm_x4(ao[1], aAddr1 + kb + 32);
            #pragma unroll
            for (int jj = 0; jj < 6; ++jj) {
                mma_f16(c1[0][jj], ao[0], bv[jj].z, bv[jj].w);
                mma_f16(c1[1][jj], ao[1], bv[jj].z, bv[jj].w);
            }
            #pragma unroll
            for (int jj = 0; jj < 6; ++jj) bv[jj] = bn[jj];
        }
    }
    __syncthreads();   // all A reads done -> region becomes H

    // ---- epilogue 1: +b1, mish, fp16, store H ----
    #pragma unroll
    for (int jj = 0; jj < 6; ++jj) {
        int col = wc * 48 + jj * 8 + 2 * tk;
        float bx = __ldg(b1c + col), by = __ldg(b1c + col + 1);
        #pragma unroll
        for (int i = 0; i < 2; ++i) {
            int row = i * 16 + tg;
            __half2 h0 = __floats2half2_rn(mish_fast(c1[i][jj][0] + bx),
                                           mish_fast(c1[i][jj][1] + by));
            __half2 h1 = __floats2half2_rn(mish_fast(c1[i][jj][2] + bx),
                                           mish_fast(c1[i][jj][3] + by));
            *(__half2*)(Hh + row * H_STR + col) = h0;
            *(__half2*)(Hh + (row + 8) * H_STR + col) = h1;
        }
    }
    __syncthreads();   // H visible

    // ================= GEMM2: [32,384] @ W2 -> [32,256] =================
    float c2[2][4][4];
    #pragma unroll
    for (int i = 0; i < 2; ++i)
        #pragma unroll
        for (int jj = 0; jj < 4; ++jj)
            #pragma unroll
            for (int u = 0; u < 4; ++u) c2[i][jj][u] = 0.f;

    {
        const __half* Wb = g_W2h + ((wc * 32 + tg) << 5) + (tk << 3);
        uint4 bv[4], bn[4];
        #pragma unroll
        for (int jj = 0; jj < 4; ++jj)
            bv[jj] = *(const uint4*)(Wb + jj * 256);

        for (int ktp = 0; ktp < 12; ++ktp) {
            const uint32_t kb = (uint32_t)(ktp << 6);
            uint32_t ae[2][4], ao[2][4];
            ldsm_x4(ae[0], hAddr0 + kb);
            ldsm_x4(ae[1], hAddr1 + kb);
            if (ktp + 1 < 12) {
                const __half* Wn = Wb + (ktp + 1) * 8192;
                #pragma unroll
                for (int jj = 0; jj < 4; ++jj)
                    bn[jj] = *(const uint4*)(Wn + jj * 256);
            }
            #pragma unroll
            for (int jj = 0; jj < 4; ++jj) {
                mma_f16(c2[0][jj], ae[0], bv[jj].x, bv[jj].y);
                mma_f16(c2[1][jj], ae[1], bv[jj].x, bv[jj].y);
            }
            ldsm_x4(ao[0], hAddr0 + kb + 32);
            ldsm_x4(ao[1], hAddr1 + kb + 32);
            #pragma unroll
            for (int jj = 0; jj < 4; ++jj) {
                mma_f16(c2[0][jj], ao[0], bv[jj].z, bv[jj].w);
                mma_f16(c2[1][jj], ao[1], bv[jj].z, bv[jj].w);
            }
            #pragma unroll
            for (int jj = 0; jj < 4; ++jj) bv[jj] = bn[jj];
        }
    }

    // ---- output: +b2, mask, store ----
    #pragma unroll
    for (int jj = 0; jj < 4; ++jj) {
        int col = wc * 32 + jj * 8 + 2 * tk;
        float bx = __ldg(b2c + col), by = __ldg(b2c + col + 1);
        #pragma unroll
        for (int i = 0; i < 2; ++i) {
            int row = i * 16 + tg;
            float2 o0, o1;
            bool v0 = (r0 + row) < n, v1 = (r0 + row + 8) < n;
            o0.x = v0 ? c2[i][jj][0] + bx : 0.f;
            o0.y = v0 ? c2[i][jj][1] + by : 0.f;
            o1.x = v1 ? c2[i][jj][2] + bx : 0.f;
            o1.y = v1 ? c2[i][jj][3] + by : 0.f;
            *(float2*)(outb + (size_t)row * DIM_OUT + col) = o0;
            *(float2*)(outb + (size_t)(row + 8) * DIM_OUT + col) = o1;
        }
    }
}

// ===================== launch =====================
extern "C" void kernel_launch(void* const* d_in, const int* in_sizes, int n_in,
                              void* d_out, int out_size)
{
    const float* z     = (const float*)d_in[0];
    const float* sp_W1 = (const float*)d_in[1];
    const float* sp_b1 = (const float*)d_in[2];
    const float* sp_g  = (const float*)d_in[3];
    const float* sp_be = (const float*)d_in[4];
    const float* sp_W2 = (const float*)d_in[5];
    const float* sp_b2 = (const float*)d_in[6];
    const float* kn_W1 = (const float*)d_in[7];
    const float* kn_b1 = (const float*)d_in[8];
    const float* kn_g  = (const float*)d_in[9];
    const float* kn_be = (const float*)d_in[10];
    const float* kn_W2 = (const float*)d_in[11];
    const float* kn_b2 = (const float*)d_in[12];
    const float* de_W1 = (const float*)d_in[13];
    const float* de_b1 = (const float*)d_in[14];
    const float* de_W2 = (const float*)d_in[15];
    const float* de_b2 = (const float*)d_in[16];
    float* out = (float*)d_out;

    long long osz = (long long)out_size;
    int write_n    = (osz >= X_SIZE + B_DIM) ? 1 : 0;
    int write_mask = (osz >= X_SIZE + B_DIM + (long long)B_DIM * MAXN) ? 1 : 0;

    cudaFuncSetAttribute(decoder_kernel,
                         cudaFuncAttributeMaxDynamicSharedMemorySize,
                         DEC_SMEM_BYTES);

    sizepred_kernel<<<256, 512>>>(z, sp_W1, sp_b1, sp_g, sp_be, sp_W2, sp_b2,
                                  out, write_n, write_mask);
    keysprep_kernel<<<704, 512>>>(kn_W1, kn_b1, kn_g, kn_be, kn_W2, kn_b2,
                                  de_W1, de_W2);
    decoder_kernel<<<B_DIM * 4, 256, DEC_SMEM_BYTES>>>(z, de_b1, de_b2, out);
}

// round 16
// speedup vs baseline: 1.5175x; 1.0486x over previous
#include <cuda_runtime.h>
#include <cuda_fp16.h>
#include <math.h>
#include <cstdint>

#define B_DIM   2048
#define HID     512
#define DIM_OUT 256
#define MAXN    128
#define MID_S   256
#define MID_K   320
#define MID_D   384

#define X_SIZE  (2048LL*128*256)
#define N_OFF   X_SIZE
#define MASK_OFF (X_SIZE + 2048LL)

__device__ __align__(16) float g_keys[MAXN * HID];
__device__ int   g_n[B_DIM];
// W1^T fp16, k32 chunks, lane-group interleaved (see prep branch)
__device__ __align__(16) __half g_W1h[16 * 384 * 32];
__device__ __align__(16) __half g_W2h[12 * 256 * 32];

__device__ __forceinline__ float mishf(float x) {
    float sp = fmaxf(x, 0.f) + log1pf(expf(-fabsf(x)));
    return x * tanhf(sp);
}
__device__ __forceinline__ float rcp_fast(float x) {
    float r;
    asm("rcp.approx.f32 %0, %1;" : "=f"(r) : "f"(x));
    return r;
}
__device__ __forceinline__ float mish_fast(float x) {
    float e = __expf(x);
    float y = 1.f + e;
    float d = fmaf(y, y, 1.f);
    return x - 2.f * x * rcp_fast(d);
}
__device__ __forceinline__ void mma_f16(float* c, const uint32_t* a,
                                        uint32_t b0, uint32_t b1) {
    asm volatile(
        "mma.sync.aligned.m16n8k16.row.col.f32.f16.f16.f32 "
        "{%0,%1,%2,%3}, {%4,%5,%6,%7}, {%8,%9}, {%0,%1,%2,%3};"
        : "+f"(c[0]), "+f"(c[1]), "+f"(c[2]), "+f"(c[3])
        : "r"(a[0]), "r"(a[1]), "r"(a[2]), "r"(a[3]), "r"(b0), "r"(b1));
}
__device__ __forceinline__ void ldsm_x4(uint32_t* r, uint32_t addr) {
    asm volatile(
        "ldmatrix.sync.aligned.m8n8.x4.shared.b16 {%0,%1,%2,%3}, [%4];"
        : "=r"(r[0]), "=r"(r[1]), "=r"(r[2]), "=r"(r[3]) : "r"(addr));
}
__device__ __forceinline__ uint32_t smem_u32(const void* p) {
    uint32_t a;
    asm("{ .reg .u64 t; cvta.to.shared.u64 t, %1; cvt.u32.u64 %0, t; }" : "=r"(a) : "l"(p));
    return a;
}

// ===================== Fused frontend: sizepred + keys + W-prep ================
// blocks [0,256): sizepred (8 rows, split-K, 512 thr)
// blocks [256,384): keys (k = blockIdx.x - 256)
// blocks [384,960): prep (576*512 ids)
#define W1H_TOTAL (16 * 384 * 32)   // 196608
#define W2H_TOTAL (12 * 256 * 32)   // 98304

__global__ __launch_bounds__(512)
void frontend_kernel(const float* __restrict__ z,
                     const float* __restrict__ W1, const float* __restrict__ b1,
                     const float* __restrict__ g,  const float* __restrict__ be,
                     const float* __restrict__ W2, const float* __restrict__ b2,
                     const float* __restrict__ kW1, const float* __restrict__ kb1,
                     const float* __restrict__ kg,  const float* __restrict__ kbe,
                     const float* __restrict__ kW2, const float* __restrict__ kb2,
                     const float* __restrict__ dW1, const float* __restrict__ dW2,
                     float* __restrict__ out, int write_n, int write_mask)
{
    const int tid = threadIdx.x;

    // ---------------- prep branch ----------------
    if (blockIdx.x >= 384) {
        int id = (blockIdx.x - 384) * 512 + tid;
        if (id < W1H_TOTAL) {
            int ktp = id / 12288, rem = id % 12288;
            int nn = rem >> 5, h = rem & 31;
            int tk = h >> 3, pos = h & 7;
            int sub = pos & 3;
            int kl = ((pos >> 2) << 4) + ((sub < 2) ? (2 * tk + sub) : (2 * tk + 8 + sub - 2));
            g_W1h[id] = __float2half_rn(dW1[(size_t)(ktp * 32 + kl) * MID_D + nn]);
        } else if (id < W1H_TOTAL + W2H_TOTAL) {
            int t = id - W1H_TOTAL;
            int ktp = t / 8192, rem = t % 8192;
            int nn = rem >> 5, h = rem & 31;
            int tk = h >> 3, pos = h & 7;
            int sub = pos & 3;
            int kl = ((pos >> 2) << 4) + ((sub < 2) ? (2 * tk + sub) : (2 * tk + 8 + sub - 2));
            g_W2h[t] = __float2half_rn(dW2[(size_t)(ktp * 32 + kl) * DIM_OUT + nn]);
        }
        return;
    }

    // ---------------- keys branch ----------------
    if (blockIdx.x >= 256) {
        __shared__ float hs[MID_K];
        __shared__ float warp_s[16], warp_s2[16];
        __shared__ float st_mean, st_rstd;
        const int k = blockIdx.x - 256;
        const bool act = tid < MID_K;
        float v = 0.f;
        if (act) v = kW1[(size_t)k * MID_K + tid] + kb1[tid];
        float s = v, s2 = v * v;
        #pragma unroll
        for (int o = 16; o; o >>= 1) {
            s  += __shfl_xor_sync(0xffffffffu, s,  o);
            s2 += __shfl_xor_sync(0xffffffffu, s2, o);
        }
        const int wid = tid >> 5, lane = tid & 31;
        if (lane == 0) { warp_s[wid] = s; warp_s2[wid] = s2; }
        __syncthreads();
        if (wid == 0) {
            float ps  = (lane < 16) ? warp_s[lane]  : 0.f;
            float ps2 = (lane < 16) ? warp_s2[lane] : 0.f;
            #pragma unroll
            for (int o = 8; o; o >>= 1) {
                ps  += __shfl_xor_sync(0xffffffffu, ps,  o);
                ps2 += __shfl_xor_sync(0xffffffffu, ps2, o);
            }
            if (lane == 0) {
                float m = ps * (1.f / MID_K);
                float var = ps2 * (1.f / MID_K) - m * m;
                st_mean = m;
                st_rstd = rsqrtf(var + 1e-5f);
            }
        }
        __syncthreads();
        if (act) hs[tid] = mishf((v - st_mean) * st_rstd * kg[tid] + kbe[tid]);
        __syncthreads();
        const int o = tid;
        float acc = kb2[o];
        for (int jj = 0; jj < MID_K; jj += 4) {
            #pragma unroll
            for (int u = 0; u < 4; ++u)
                acc = fmaf(hs[jj + u], kW2[(size_t)(jj + u) * HID + o], acc);
        }
        g_keys[(size_t)k * HID + o] = acc;
        return;
    }

    // ---------------- sizepred branch (split-K, 8 rows) ----------------
    __shared__ float zsh[8][HID];       // 16 KB
    __shared__ float hsh[8][MID_S];     // 8 KB
    __shared__ float psh[8][MID_S];     // 8 KB
    __shared__ float smean[8], srstd[8];
    __shared__ int   nsh[8];
    const int b0 = blockIdx.x * 8;

    {
        const float4* z4 = (const float4*)(z + (size_t)b0 * HID);
        float4* zs4 = (float4*)zsh;
        #pragma unroll
        for (int e = 0; e < 2; ++e) zs4[e * 512 + tid] = z4[e * 512 + tid];
    }
    __syncthreads();

    const int j  = tid & 255;
    const int kh = tid >> 8;
    float acc[8];
    {
        float bj = (kh == 0) ? b1[j] : 0.f;
        #pragma unroll
        for (int bb = 0; bb < 8; ++bb) acc[bb] = bj;
    }
    const int kbase = kh * 256;
    for (int i = 0; i < 256; i += 8) {
        #pragma unroll
        for (int ii = 0; ii < 8; ++ii) {
            float w = W1[(size_t)(kbase + i + ii) * MID_S + j];
            #pragma unroll
            for (int bb = 0; bb < 8; ++bb)
                acc[bb] = fmaf(zsh[bb][kbase + i + ii], w, acc[bb]);
        }
    }
    {
        float (*dst)[MID_S] = (kh == 0) ? hsh : psh;
        #pragma unroll
        for (int bb = 0; bb < 8; ++bb) dst[bb][j] = acc[bb];
    }
    __syncthreads();

    if (kh == 0) {
        #pragma unroll
        for (int bb = 0; bb < 8; ++bb) hsh[bb][j] += psh[bb][j];
    }
    __syncthreads();

    const int wid = tid >> 5, lane = tid & 31;
    if (wid < 8) {
        float s = 0.f, s2 = 0.f;
        for (int jj = lane; jj < MID_S; jj += 32) {
            float v = hsh[wid][jj];
            s += v; s2 += v * v;
        }
        #pragma unroll
        for (int o = 16; o; o >>= 1) {
            s  += __shfl_xor_sync(0xffffffffu, s,  o);
            s2 += __shfl_xor_sync(0xffffffffu, s2, o);
        }
        if (lane == 0) {
            float m = s * (1.f / MID_S);
            float var = s2 * (1.f / MID_S) - m * m;
            smean[wid] = m;
            srstd[wid] = rsqrtf(var + 1e-5f);
        }
    }
    __syncthreads();

    #pragma unroll
    for (int e = 0; e < 4; ++e) {
        int lin = e * 512 + tid;
        int bb = lin >> 8, jj = lin & 255;
        float v = (hsh[bb][jj] - smean[bb]) * srstd[bb] * g[jj] + be[jj];
        hsh[bb][jj] = mishf(v) * W2[jj];
    }
    __syncthreads();

    if (wid < 8) {
        float s = 0.f;
        for (int jj = lane; jj < MID_S; jj += 32) s += hsh[wid][jj];
        #pragma unroll
        for (int o = 16; o; o >>= 1) s += __shfl_xor_sync(0xffffffffu, s, o);
        if (lane == 0) {
            float logit = s + b2[0];
            float nf = fminf(fmaxf(rintf(logit), 0.f), (float)MAXN);
            int ni = (int)nf;
            g_n[b0 + wid] = ni;
            nsh[wid] = ni;
            if (write_n) out[N_OFF + b0 + wid] = nf;
        }
    }
    __syncthreads();

    if (write_mask) {
        #pragma unroll
        for (int e = 0; e < 2; ++e) {
            int lin = e * 512 + tid;
            int bb = lin >> 7, kk = lin & 127;
            out[MASK_OFF + (size_t)(b0 + bb) * MAXN + kk] = (kk < nsh[bb]) ? 1.f : 0.f;
        }
    }
}

// ===================== Kernel C: fp16 mma decoder + ldmatrix, 2 CTAs/SM ========
// A smem: [32 rows][520 halves]; rows 1040 B apart -> 260 words, 260%32=4 ->
// ldmatrix 8-row phases hit disjoint bank quads (conflict-free). H: [32][392].
#define A_STR 520
#define H_STR 392
#define ZS_BYTE_OFF 33280                    // 32*520*2
#define DEC_SMEM_BYTES (ZS_BYTE_OFF + 2048)  // 35328

__global__ __launch_bounds__(256, 2)
void decoder_kernel(const float* __restrict__ z,
                    const float* __restrict__ b1c,
                    const float* __restrict__ b2c,
                    float* __restrict__ out)
{
    extern __shared__ char smraw[];
    __half* Ah = (__half*)smraw;
    __half* Hh = (__half*)smraw;
    float*  zs = (float*)(smraw + ZS_BYTE_OFF);

    const int b    = blockIdx.x >> 2;
    const int r0   = (blockIdx.x & 3) * 32;
    const int tid  = threadIdx.x;
    const int wc   = tid >> 5;          // 0..7 warp col
    const int lane = tid & 31;
    const int tg   = lane >> 2;         // 0..7
    const int tk   = lane & 3;          // 0..3

    const int n = g_n[b];
    float* outb = out + (size_t)b * MAXN * DIM_OUT + (size_t)r0 * DIM_OUT;

    if (r0 >= n) {
        float4 zz = make_float4(0.f, 0.f, 0.f, 0.f);
        float4* o4 = (float4*)outb;
        #pragma unroll
        for (int e = 0; e < 8; ++e) o4[e * 256 + tid] = zz;
        return;
    }

    zs[tid] = z[(size_t)b * HID + tid];
    zs[256 + tid] = z[(size_t)b * HID + 256 + tid];
    __syncthreads();

    const float4* K4 = (const float4*)g_keys;
    const float4* Z4 = (const float4*)zs;

    // ---- build A (fp16): A[r][k] = half(keys[r0+r][k] * z[k]) ----
    #pragma unroll
    for (int e = 0; e < 16; ++e) {
        int idx = e * 256 + tid;        // 0..4095
        int r = idx >> 7, q = idx & 127;
        float4 kv = K4[(size_t)(r0 + r) * 128 + q];
        float4 zv = Z4[q];
        __half2 h0 = __floats2half2_rn(kv.x * zv.x, kv.y * zv.y);
        __half2 h1 = __floats2half2_rn(kv.z * zv.z, kv.w * zv.w);
        uint2 pk;
        pk.x = *(uint32_t*)&h0;
        pk.y = *(uint32_t*)&h1;
        *(uint2*)(Ah + r * A_STR + q * 4) = pk;
    }
    __syncthreads();   // A visible

    // ldmatrix lane addressing
    const int rowl = lane & 15;
    const int colg = (lane >> 4) << 3;
    const uint32_t smbA = smem_u32(Ah);
    const uint32_t aAddr0 = smbA + (uint32_t)(rowl * A_STR + colg) * 2;
    const uint32_t aAddr1 = smbA + (uint32_t)((16 + rowl) * A_STR + colg) * 2;
    const uint32_t hAddr0 = smbA + (uint32_t)(rowl * H_STR + colg) * 2;
    const uint32_t hAddr1 = smbA + (uint32_t)((16 + rowl) * H_STR + colg) * 2;

    // ================= GEMM1: [32,512] @ W1 -> [32,384] =================
    float c1[2][6][4];
    #pragma unroll
    for (int i = 0; i < 2; ++i)
        #pragma unroll
        for (int jj = 0; jj < 6; ++jj)
            #pragma unroll
            for (int u = 0; u < 4; ++u) c1[i][jj][u] = 0.f;

    {
        const __half* Wb = g_W1h + ((wc * 48 + tg) << 5) + (tk << 3);
        uint4 bv[6], bn[6];
        #pragma unroll
        for (int jj = 0; jj < 6; ++jj)
            bv[jj] = *(const uint4*)(Wb + jj * 256);

        for (int ktp = 0; ktp < 16; ++ktp) {
            const uint32_t kb = (uint32_t)(ktp << 6);   // k0*2 bytes
            uint32_t ae[2][4], ao[2][4];
            ldsm_x4(ae[0], aAddr0 + kb);
            ldsm_x4(ae[1], aAddr1 + kb);
            if (ktp + 1 < 16) {
                const __half* Wn = Wb + (ktp + 1) * 12288;
                #pragma unroll
                for (int jj = 0; jj < 6; ++jj)
                    bn[jj] = *(const uint4*)(Wn + jj * 256);
            }
            #pragma unroll
            for (int jj = 0; jj < 6; ++jj) {
                mma_f16(c1[0][jj], ae[0], bv[jj].x, bv[jj].y);
                mma_f16(c1[1][jj], ae[1], bv[jj].x, bv[jj].y);
            }
            ldsm_x4(ao[0], aAddr0 + kb + 32);
            ldsm_x4(ao[1], aAddr1 + kb + 32);
            #pragma unroll
            for (int jj = 0; jj < 6; ++jj) {
                mma_f16(c1[0][jj], ao[0], bv[jj].z, bv[jj].w);
                mma_f16(c1[1][jj], ao[1], bv[jj].z, bv[jj].w);
            }
            #pragma unroll
            for (int jj = 0; jj < 6; ++jj) bv[jj] = bn[jj];
        }
    }
    __syncthreads();   // all A reads done -> region becomes H

    // ---- epilogue 1: +b1, mish, fp16, store H ----
    #pragma unroll
    for (int jj = 0; jj < 6; ++jj) {
        int col = wc * 48 + jj * 8 + 2 * tk;
        float bx = __ldg(b1c + col), by = __ldg(b1c + col + 1);
        #pragma unroll
        for (int i = 0; i < 2; ++i) {
            int row = i * 16 + tg;
            __half2 h0 = __floats2half2_rn(mish_fast(c1[i][jj][0] + bx),
                                           mish_fast(c1[i][jj][1] + by));
            __half2 h1 = __floats2half2_rn(mish_fast(c1[i][jj][2] + bx),
                                           mish_fast(c1[i][jj][3] + by));
            *(__half2*)(Hh + row * H_STR + col) = h0;
            *(__half2*)(Hh + (row + 8) * H_STR + col) = h1;
        }
    }
    __syncthreads();   // H visible

    // ================= GEMM2: [32,384] @ W2 -> [32,256] =================
    float c2[2][4][4];
    #pragma unroll
    for (int i = 0; i < 2; ++i)
        #pragma unroll
        for (int jj = 0; jj < 4; ++jj)
            #pragma unroll
            for (int u = 0; u < 4; ++u) c2[i][jj][u] = 0.f;

    {
        const __half* Wb = g_W2h + ((wc * 32 + tg) << 5) + (tk << 3);
        uint4 bv[4], bn[4];
        #pragma unroll
        for (int jj = 0; jj < 4; ++jj)
            bv[jj] = *(const uint4*)(Wb + jj * 256);

        for (int ktp = 0; ktp < 12; ++ktp) {
            const uint32_t kb = (uint32_t)(ktp << 6);
            uint32_t ae[2][4], ao[2][4];
            ldsm_x4(ae[0], hAddr0 + kb);
            ldsm_x4(ae[1], hAddr1 + kb);
            if (ktp + 1 < 12) {
                const __half* Wn = Wb + (ktp + 1) * 8192;
                #pragma unroll
                for (int jj = 0; jj < 4; ++jj)
                    bn[jj] = *(const uint4*)(Wn + jj * 256);
            }
            #pragma unroll
            for (int jj = 0; jj < 4; ++jj) {
                mma_f16(c2[0][jj], ae[0], bv[jj].x, bv[jj].y);
                mma_f16(c2[1][jj], ae[1], bv[jj].x, bv[jj].y);
            }
            ldsm_x4(ao[0], hAddr0 + kb + 32);
            ldsm_x4(ao[1], hAddr1 + kb + 32);
            #pragma unroll
            for (int jj = 0; jj < 4; ++jj) {
                mma_f16(c2[0][jj], ao[0], bv[jj].z, bv[jj].w);
                mma_f16(c2[1][jj], ao[1], bv[jj].z, bv[jj].w);
            }
            #pragma unroll
            for (int jj = 0; jj < 4; ++jj) bv[jj] = bn[jj];
        }
    }

    // ---- output: +b2, mask, store ----
    #pragma unroll
    for (int jj = 0; jj < 4; ++jj) {
        int col = wc * 32 + jj * 8 + 2 * tk;
        float bx = __ldg(b2c + col), by = __ldg(b2c + col + 1);
        #pragma unroll
        for (int i = 0; i < 2; ++i) {
            int row = i * 16 + tg;
            float2 o0, o1;
            bool v0 = (r0 + row) < n, v1 = (r0 + row + 8) < n;
            o0.x = v0 ? c2[i][jj][0] + bx : 0.f;
            o0.y = v0 ? c2[i][jj][1] + by : 0.f;
            o1.x = v1 ? c2[i][jj][2] + bx : 0.f;
            o1.y = v1 ? c2[i][jj][3] + by : 0.f;
            *(float2*)(outb + (size_t)row * DIM_OUT + col) = o0;
            *(float2*)(outb + (size_t)(row + 8) * DIM_OUT + col) = o1;
        }
    }
}

// ===================== launch =====================
extern "C" void kernel_launch(void* const* d_in, const int* in_sizes, int n_in,
                              void* d_out, int out_size)
{
    const float* z     = (const float*)d_in[0];
    const float* sp_W1 = (const float*)d_in[1];
    const float* sp_b1 = (const float*)d_in[2];
    const float* sp_g  = (const float*)d_in[3];
    const float* sp_be = (const float*)d_in[4];
    const float* sp_W2 = (const float*)d_in[5];
    const float* sp_b2 = (const float*)d_in[6];
    const float* kn_W1 = (const float*)d_in[7];
    const float* kn_b1 = (const float*)d_in[8];
    const float* kn_g  = (const float*)d_in[9];
    const float* kn_be = (const float*)d_in[10];
    const float* kn_W2 = (const float*)d_in[11];
    const float* kn_b2 = (const float*)d_in[12];
    const float* de_W1 = (const float*)d_in[13];
    const float* de_b1 = (const float*)d_in[14];
    const float* de_W2 = (const float*)d_in[15];
    const float* de_b2 = (const float*)d_in[16];
    float* out = (float*)d_out;

    long long osz = (long long)out_size;
    int write_n    = (osz >= X_SIZE + B_DIM) ? 1 : 0;
    int write_mask = (osz >= X_SIZE + B_DIM + (long long)B_DIM * MAXN) ? 1 : 0;

    cudaFuncSetAttribute(decoder_kernel,
                         cudaFuncAttributeMaxDynamicSharedMemorySize,
                         DEC_SMEM_BYTES);

    frontend_kernel<<<960, 512>>>(z, sp_W1, sp_b1, sp_g, sp_be, sp_W2, sp_b2,
                                  kn_W1, kn_b1, kn_g, kn_be, kn_W2, kn_b2,
                                  de_W1, de_W2,
                                  out, write_n, write_mask);
    decoder_kernel<<<B_DIM * 4, 256, DEC_SMEM_BYTES>>>(z, de_b1, de_b2, out);
}